// round 5
// baseline (speedup 1.0000x reference)
#include <cuda_runtime.h>
#include <math.h>

#define NG 192
#define VX 64            // voxels per block in x
#define BX 32            // threads in x (2 voxels each)
#define BY 4
#define BZ 4
#define TX2 (VX + 4)     // 68 tile cols
#define TY (BY + 4)      // 8
#define TZ (BZ + 4)      // 8
#define TILE2 (TX2 * TY * TZ)   // 4352
#define ROWU2 (TX2 / 2)         // 34 uint2 per row
#define NTOT (NG * NG * NG)

#define KN   500000.0f
#define MU   0.5f
#define EPSF 1e-4f
#define FULLMASK 0xffffffffu
#define BMASK 0x00FEFEFEu

__device__ __forceinline__ int wrapN(int v) {
    if (v < 0) v += NG;
    if (v >= NG) v -= NG;
    return v;
}

__device__ __forceinline__ unsigned tstk(unsigned p, unsigned k) {
    return __vabsdiffu4(p, k) & BMASK;   // ==0 iff all 3 byte-diffs <= 1
}

// exact per-voxel accumulation (rare path); positions from smem, vels global
__device__ __noinline__ void exact_voxel(
    const float2* __restrict__ sxy, const float* __restrict__ szs,
    int cz, int cy, int cx, int ga, int gb, int gc,
    float px, float py, float pz,
    float two_d, float two_d2, float eta,
    const float* __restrict__ vxg, const float* __restrict__ vyg,
    const float* __restrict__ vzg,
    float& fxc, float& fyc, float& fzc,
    float& fxd, float& fyd, float& fzd)
{
    const int gidx = (ga * NG + gb) * NG + gc;
    const float pvx = vxg[gidx], pvy = vyg[gidx], pvz = vzg[gidx];
    #pragma unroll 1
    for (int oz = -2; oz <= 2; oz++) {
        #pragma unroll 1
        for (int oy = -2; oy <= 2; oy++) {
            const int rb = ((cz + oz) * TY + (cy + oy)) * TX2 + cx;
            #pragma unroll 1
            for (int ox = -2; ox <= 2; ox++) {
                const float2 nxy = sxy[rb + ox];
                const float dx = px - nxy.x;
                const float dy = py - nxy.y;
                const float dz = pz - szs[rb + ox];
                const float d2 = fmaf(dz, dz, fmaf(dy, dy, dx * dx));
                const bool hit = (d2 < two_d2) && (d2 > 0.0f);
                if (hit) {
                    const float dist = sqrtf(d2);
                    const float safe = fmaxf(EPSF, dist);
                    const float inv  = 1.0f / safe;
                    const float coef = KN * (dist - two_d) * inv;
                    fxc += coef * dx;
                    fyc += coef * dy;
                    fzc += coef * dz;
                    const int na = wrapN(ga + oz);
                    const int nb = wrapN(gb + oy);
                    const int nc = wrapN(gc + ox);
                    const int nidx = (na * NG + nb) * NG + nc;
                    const float dvx = pvx - vxg[nidx];
                    const float dvy = pvy - vyg[nidx];
                    const float dvz = pvz - vzg[nidx];
                    const float vn  = (dvx * dx + dvy * dy + dvz * dz) * inv;
                    const float c2  = eta * vn * inv;
                    fxd += c2 * dx;
                    fyd += c2 * dy;
                    fzd += c2 * dz;
                }
            }
        }
    }
}

__global__ __launch_bounds__(BX * BY * BZ, 2)
void dem_kernel(const float* __restrict__ xg, const float* __restrict__ yg,
                const float* __restrict__ zg, const float* __restrict__ vxg,
                const float* __restrict__ vyg, const float* __restrict__ vzg,
                const float* __restrict__ dptr, float* __restrict__ out,
                float eta)
{
    __shared__ float2   sxy[TILE2];              // exact fp32 (x,y)
    __shared__ float    szs[TILE2];              // exact fp32 z
    __shared__ uint2    qpk2[TZ * TY * ROWU2];   // packed byte keys, 2 cols/entry

    unsigned* qpku = (unsigned*)qpk2;

    const int lx = threadIdx.x, ly = threadIdx.y, lz = threadIdx.z;
    const int bx0 = blockIdx.x * VX;
    const int by0 = blockIdx.y * BY;
    const int bz0 = blockIdx.z * BZ;
    const int tid = (lz * BY + ly) * BX + lx;

    // --- cooperative halo load + key build ---
    for (int idx = tid; idx < TILE2; idx += BX * BY * BZ) {
        int txi = idx % TX2;
        int rem = idx / TX2;
        int tyi = rem % TY;
        int tzi = rem / TY;
        int gx = wrapN(bx0 + txi - 2);
        int gy = wrapN(by0 + tyi - 2);
        int gz = wrapN(bz0 + tzi - 2);
        int g = (gz * NG + gy) * NG + gx;
        float x = xg[g], y = yg[g], z = zg[g];
        sxy[idx] = make_float2(x, y);
        szs[idx] = z;
        qpku[idx] = (unsigned)(int)x | ((unsigned)(int)y << 8)
                  | ((unsigned)(int)z << 16);
    }
    __syncthreads();

    const float d      = *dptr;
    const float two_d  = 2.0f * d;
    const float two_d2 = two_d * two_d;
    const bool  filter_ok = (two_d <= 1.0f);   // byte filter validity

    const int cz = lz + 2, cy = ly + 2;
    const int cx0 = 2 * lx + 2;                // voxel0 tile col; voxel1 = +1
    const int cidx0 = (cz * TY + cy) * TX2 + cx0;
    const unsigned pq0 = qpku[cidx0];
    const unsigned pq1 = qpku[cidx0 + 1];
    const float2 pxy0 = sxy[cidx0];
    const float2 pxy1 = sxy[cidx0 + 1];
    const float pz0 = szs[cidx0], pz1 = szs[cidx0 + 1];

    const int ga = bz0 + lz, gb = by0 + ly;
    const int gc0 = bx0 + 2 * lx;
    const int gidx0 = (ga * NG + gb) * NG + gc0;

    float fxc0 = 0.f, fyc0 = 0.f, fzc0 = 0.f, fxd0 = 0.f, fyd0 = 0.f, fzd0 = 0.f;
    float fxc1 = 0.f, fyc1 = 0.f, fzc1 = 0.f, fxd1 = 0.f, fyd1 = 0.f, fzd1 = 0.f;

    // ---- byte prefilter: 3 LDS.64/row serve both voxels; one vote total ----
    bool need0 = !filter_ok, need1 = !filter_ok;
    if (filter_ok) {
        unsigned a0 = ~0u, a1 = ~0u;   // voxel0 min-accumulators
        unsigned b0 = ~0u, b1 = ~0u;   // voxel1
        #pragma unroll
        for (int oz = -2; oz <= 2; oz++) {
            #pragma unroll
            for (int oy = -2; oy <= 2; oy++) {
                const int ru = ((cz + oz) * TY + (cy + oy)) * ROWU2 + lx;
                const uint2 w0 = qpk2[ru];
                const uint2 w1 = qpk2[ru + 1];
                const uint2 w2 = qpk2[ru + 2];
                const unsigned k0 = w0.x, k1 = w0.y, k2 = w1.x;
                const unsigned k3 = w1.y, k4 = w2.x, k5 = w2.y;
                if (oz == 0 && oy == 0) {
                    // voxel0 self = k2, voxel1 self = k3 -> skip those
                    a0 = min(a0, tstk(pq0, k0));
                    a1 = min(a1, tstk(pq0, k1));
                    a0 = min(a0, tstk(pq0, k3));
                    a1 = min(a1, tstk(pq0, k4));
                    b0 = min(b0, tstk(pq1, k1));
                    b1 = min(b1, tstk(pq1, k2));
                    b0 = min(b0, tstk(pq1, k4));
                    b1 = min(b1, tstk(pq1, k5));
                } else {
                    a0 = min(a0, tstk(pq0, k0));
                    a1 = min(a1, tstk(pq0, k1));
                    a0 = min(a0, tstk(pq0, k2));
                    a1 = min(a1, tstk(pq0, k3));
                    a0 = min(a0, tstk(pq0, k4));
                    b0 = min(b0, tstk(pq1, k1));
                    b1 = min(b1, tstk(pq1, k2));
                    b0 = min(b0, tstk(pq1, k3));
                    b1 = min(b1, tstk(pq1, k4));
                    b0 = min(b0, tstk(pq1, k5));
                }
            }
        }
        need0 = (min(a0, a1) == 0u);
        need1 = (min(b0, b1) == 0u);
    }

    // ---- exact fallback (rare: ~3% of warps) ----
    if (__any_sync(FULLMASK, need0 || need1)) {
        exact_voxel(sxy, szs, cz, cy, cx0,     ga, gb, gc0,
                    pxy0.x, pxy0.y, pz0, two_d, two_d2, eta,
                    vxg, vyg, vzg, fxc0, fyc0, fzc0, fxd0, fyd0, fzd0);
        exact_voxel(sxy, szs, cz, cy, cx0 + 1, ga, gb, gc0 + 1,
                    pxy1.x, pxy1.y, pz1, two_d, two_d2, eta,
                    vxg, vyg, vzg, fxc1, fyc1, fzc1, fxd1, fyd1, fzd1);
    }

    // ---- friction: only the LAST scan shift s=(2,2,2) survives, i.e.
    //      neighbor offset (-2,-2,-2), against the fully accumulated sums. ----
    float frx0 = 0.f, fry0 = 0.f, frz0 = 0.f;
    float frx1 = 0.f, fry1 = 0.f, frz1 = 0.f;
    {
        const int rbs = ((cz - 2) * TY + (cy - 2)) * TX2 + (cx0 - 2);
        bool f0 = !filter_ok || (tstk(pq0, qpku[rbs]) == 0u);
        bool f1 = !filter_ok || (tstk(pq1, qpku[rbs + 1]) == 0u);
        if (__any_sync(FULLMASK, f0 || f1)) {
            const int na = wrapN(ga - 2);
            const int nb = wrapN(gb - 2);
            #pragma unroll
            for (int v = 0; v < 2; v++) {
                const bool fv = v ? f1 : f0;
                if (!fv) continue;
                const int cc  = cx0 + v;
                const int gcc = gc0 + v;
                const float2 pxy = v ? pxy1 : pxy0;
                const float  pzv = v ? pz1 : pz0;
                const int rb = rbs + v;
                const float2 nxy = sxy[rb];
                const float dx = pxy.x - nxy.x;
                const float dy = pxy.y - nxy.y;
                const float dz = pzv - szs[rb];
                const float d2 = fmaf(dz, dz, fmaf(dy, dy, dx * dx));
                if (d2 < two_d2) {
                    const int gidx = (ga * NG + gb) * NG + gcc;
                    const int nc = wrapN(gcc - 2);
                    const int nidx = (na * NG + nb) * NG + nc;
                    const float dvx = vxg[gidx] - vxg[nidx];
                    const float dvy = vyg[gidx] - vyg[nidx];
                    const float dvz = vzg[gidx] - vzg[nidx];
                    const float fxc = v ? fxc1 : fxc0, fyc = v ? fyc1 : fyc0;
                    const float fzc = v ? fzc1 : fzc0, fxd = v ? fxd1 : fxd0;
                    const float fyd = v ? fyd1 : fyd0, fzd = v ? fzd1 : fzd0;
                    const float rx = -(fabsf(fabsf(MU * fyc) + fabsf(MU * fzc) - MU * fxd)
                                       * dvx / fmaxf(EPSF, fabsf(dvx)));
                    const float ry = -(fabsf(fabsf(MU * fxc) + fabsf(MU * fzc) - MU * fyd)
                                       * dvy / fmaxf(EPSF, fabsf(dvy)));
                    // NB: reference uses diffvy in the z-friction numerator (kept).
                    const float rz = -(fabsf(fabsf(MU * fxc) + fabsf(MU * fyc) - MU * fzd)
                                       * dvy / fmaxf(EPSF, fabsf(dvz)));
                    if (v) { frx1 = rx; fry1 = ry; frz1 = rz; }
                    else   { frx0 = rx; fry0 = ry; frz0 = rz; }
                }
            }
        }
    }

    // ---- outputs: x-pairs are consecutive -> float2 stores ----
    float* o = out + gidx0;
    *(float2*)(o + 0 * NTOT) = make_float2(fxc0, fxc1);
    *(float2*)(o + 1 * NTOT) = make_float2(fyc0, fyc1);
    *(float2*)(o + 2 * NTOT) = make_float2(fzc0, fzc1);
    *(float2*)(o + 3 * NTOT) = make_float2(fxd0, fxd1);
    *(float2*)(o + 4 * NTOT) = make_float2(fyd0, fyd1);
    *(float2*)(o + 5 * NTOT) = make_float2(fzd0, fzd1);
    *(float2*)(o + 6 * NTOT) = make_float2(frx0, frx1);
    *(float2*)(o + 7 * NTOT) = make_float2(fry0, fry1);
    *(float2*)(o + 8 * NTOT) = make_float2(frz0, frz1);
}

extern "C" void kernel_launch(void* const* d_in, const int* in_sizes, int n_in,
                              void* d_out, int out_size)
{
    const float* xg   = (const float*)d_in[0];
    const float* yg   = (const float*)d_in[1];
    const float* zg   = (const float*)d_in[2];
    const float* vxg  = (const float*)d_in[3];
    const float* vyg  = (const float*)d_in[4];
    const float* vzg  = (const float*)d_in[5];
    const float* dptr = (const float*)d_in[6];
    float* out = (float*)d_out;

    // ETA = 2*gamma*sqrt(KN), gamma = alpha/sqrt(alpha^2+1), alpha = -ln(0.7)/pi
    const double alpha = -log(0.7) / M_PI;
    const double gam   = alpha / sqrt(alpha * alpha + 1.0);
    const float  eta   = (float)(2.0 * gam * sqrt(500000.0));

    dim3 block(BX, BY, BZ);
    dim3 grid(NG / VX, NG / BY, NG / BZ);
    dem_kernel<<<grid, block>>>(xg, yg, zg, vxg, vyg, vzg, dptr, out, eta);
}

// round 6
// speedup vs baseline: 1.4390x; 1.4390x over previous
#include <cuda_runtime.h>
#include <math.h>

#define NG 192
#define BX 32
#define BY 4
#define BZ 4
#define TX (BX + 4)      // 36
#define TY (BY + 4)      // 8
#define TZ (BZ + 4)      // 8
#define TILE (TX * TY * TZ)   // 2304
#define NTOT (NG * NG * NG)

#define KN   500000.0f
#define MU   0.5f
#define EPSF 1e-4f
#define FULLMASK 0xffffffffu
#define BMASK 0x00FEFEFEu

__device__ __forceinline__ int wrapN(int v) {
    if (v < 0) v += NG;
    if (v >= NG) v -= NG;
    return v;
}

__global__ __launch_bounds__(BX * BY * BZ, 4)
void dem_kernel(const float* __restrict__ xg, const float* __restrict__ yg,
                const float* __restrict__ zg, const float* __restrict__ vxg,
                const float* __restrict__ vyg, const float* __restrict__ vzg,
                const float* __restrict__ dptr, float* __restrict__ out,
                float eta)
{
    __shared__ unsigned qpk[TILE];   // bytes: (floor(x), floor(y), floor(z), 0)

    const int lx = threadIdx.x, ly = threadIdx.y, lz = threadIdx.z;
    const int bx0 = blockIdx.x * BX;
    const int by0 = blockIdx.y * BY;
    const int bz0 = blockIdx.z * BZ;
    const int tid = (lz * BY + ly) * BX + lx;

    // --- cooperative halo key build (wraparound); keys only in smem ---
    for (int idx = tid; idx < TILE; idx += BX * BY * BZ) {
        int txi = idx % TX;
        int rem = idx / TX;
        int tyi = rem % TY;
        int tzi = rem / TY;
        int gx = wrapN(bx0 + txi - 2);
        int gy = wrapN(by0 + tyi - 2);
        int gz = wrapN(bz0 + tzi - 2);
        int g = (gz * NG + gy) * NG + gx;
        // coords in [0, 192): floors fit a byte
        qpk[idx] = (unsigned)(int)xg[g] | ((unsigned)(int)yg[g] << 8)
                 | ((unsigned)(int)zg[g] << 16);
    }
    __syncthreads();

    const float d      = *dptr;
    const float two_d  = 2.0f * d;
    // filter validity: |dx| < two_d <= 1  =>  |floor(x)-floor(nx)| <= 1 per axis
    const bool filter_ok = (two_d <= 1.0f);

    const int cz = lz + 2, cy = ly + 2, cx = lx + 2;
    const int cidx = (cz * TY + cy) * TX + cx;
    const unsigned pq = qpk[cidx];

    const int ga = bz0 + lz, gb = by0 + ly, gc = bx0 + lx;
    const int gidx = (ga * NG + gb) * NG + gc;

    // ---- byte prefilter: 4 instr/offset, compile-time LDS offsets, 1 vote ----
    bool need = !filter_ok;
    if (filter_ok) {
        unsigned m0 = ~0u, m1 = ~0u, m2 = ~0u, m3 = ~0u;
        #pragma unroll
        for (int oz = -2; oz <= 2; oz++) {
            #pragma unroll
            for (int oy = -2; oy <= 2; oy++) {
                #pragma unroll
                for (int ox = -2; ox <= 2; ox++) {
                    if (oz == 0 && oy == 0 && ox == 0) continue; // self: skip
                    const unsigned nq = qpk[cidx + (oz * TY + oy) * TX + ox];
                    const unsigned v = __vabsdiffu4(pq, nq) & BMASK; // 0 iff all diffs<=1
                    const int lane = ((oz + 2) * 25 + (oy + 2) * 5 + (ox + 2)) & 3;
                    if (lane == 0)      m0 = min(m0, v);
                    else if (lane == 1) m1 = min(m1, v);
                    else if (lane == 2) m2 = min(m2, v);
                    else                m3 = min(m3, v);
                }
            }
        }
        need = (min(min(m0, m1), min(m2, m3)) == 0u);
    }

    float* o = out + gidx;
    if (__any_sync(FULLMASK, need)) {
        // ================= RARE PATH (~1.5% of warps) =================
        float fxc = 0.f, fyc = 0.f, fzc = 0.f;
        float fxd = 0.f, fyd = 0.f, fzd = 0.f;
        float frx = 0.f, fry = 0.f, frz = 0.f;
        if (need) {
            const float two_d2 = two_d * two_d;
            const float px = xg[gidx], py = yg[gidx], pz = zg[gidx];
            const float pvx = vxg[gidx], pvy = vyg[gidx], pvz = vzg[gidx];
            #pragma unroll 1
            for (int oz = -2; oz <= 2; oz++) {
                const int na = wrapN(ga + oz);
                #pragma unroll 1
                for (int oy = -2; oy <= 2; oy++) {
                    const int nb = wrapN(gb + oy);
                    const int rowb = (na * NG + nb) * NG;
                    #pragma unroll 1
                    for (int ox = -2; ox <= 2; ox++) {
                        const int nc = wrapN(gc + ox);
                        const int nidx = rowb + nc;
                        const float dx = px - xg[nidx];
                        const float dy = py - yg[nidx];
                        const float dz = pz - zg[nidx];
                        const float d2 = fmaf(dz, dz, fmaf(dy, dy, dx * dx));
                        // d2 == 0 (incl. self) contributes exactly 0 -> skip
                        const bool hit = (d2 < two_d2) && (d2 > 0.0f);
                        if (hit) {
                            const float dist = sqrtf(d2);
                            const float safe = fmaxf(EPSF, dist);
                            const float inv  = 1.0f / safe;
                            const float coef = KN * (dist - two_d) * inv;
                            fxc += coef * dx;
                            fyc += coef * dy;
                            fzc += coef * dz;
                            const float dvx = pvx - vxg[nidx];
                            const float dvy = pvy - vyg[nidx];
                            const float dvz = pvz - vzg[nidx];
                            const float vn  = (dvx * dx + dvy * dy + dvz * dz) * inv;
                            const float c2  = eta * vn * inv;
                            fxd += c2 * dx;
                            fyd += c2 * dy;
                            fzd += c2 * dz;
                        }
                    }
                }
            }
            // friction: only the LAST scan shift s=(2,2,2) survives, i.e.
            // neighbor offset (-2,-2,-2), against the fully accumulated sums.
            {
                const int na = wrapN(ga - 2);
                const int nb = wrapN(gb - 2);
                const int nc = wrapN(gc - 2);
                const int nidx = (na * NG + nb) * NG + nc;
                const float dx = px - xg[nidx];
                const float dy = py - yg[nidx];
                const float dz = pz - zg[nidx];
                const float d2 = fmaf(dz, dz, fmaf(dy, dy, dx * dx));
                if (d2 < two_d2) {
                    const float dvx = pvx - vxg[nidx];
                    const float dvy = pvy - vyg[nidx];
                    const float dvz = pvz - vzg[nidx];
                    frx = -(fabsf(fabsf(MU * fyc) + fabsf(MU * fzc) - MU * fxd)
                            * dvx / fmaxf(EPSF, fabsf(dvx)));
                    fry = -(fabsf(fabsf(MU * fxc) + fabsf(MU * fzc) - MU * fyd)
                            * dvy / fmaxf(EPSF, fabsf(dvy)));
                    // NB: reference uses diffvy in the z-friction numerator (kept).
                    frz = -(fabsf(fabsf(MU * fxc) + fabsf(MU * fyc) - MU * fzd)
                            * dvy / fmaxf(EPSF, fabsf(dvz)));
                }
            }
        }
        o[0 * NTOT] = fxc;
        o[1 * NTOT] = fyc;
        o[2 * NTOT] = fzc;
        o[3 * NTOT] = fxd;
        o[4 * NTOT] = fyd;
        o[5 * NTOT] = fzd;
        o[6 * NTOT] = frx;
        o[7 * NTOT] = fry;
        o[8 * NTOT] = frz;
    } else {
        // ================= COMMON PATH: all nine forces are zero ============
        o[0 * NTOT] = 0.f;
        o[1 * NTOT] = 0.f;
        o[2 * NTOT] = 0.f;
        o[3 * NTOT] = 0.f;
        o[4 * NTOT] = 0.f;
        o[5 * NTOT] = 0.f;
        o[6 * NTOT] = 0.f;
        o[7 * NTOT] = 0.f;
        o[8 * NTOT] = 0.f;
    }
}

extern "C" void kernel_launch(void* const* d_in, const int* in_sizes, int n_in,
                              void* d_out, int out_size)
{
    const float* xg   = (const float*)d_in[0];
    const float* yg   = (const float*)d_in[1];
    const float* zg   = (const float*)d_in[2];
    const float* vxg  = (const float*)d_in[3];
    const float* vyg  = (const float*)d_in[4];
    const float* vzg  = (const float*)d_in[5];
    const float* dptr = (const float*)d_in[6];
    float* out = (float*)d_out;

    // ETA = 2*gamma*sqrt(KN), gamma = alpha/sqrt(alpha^2+1), alpha = -ln(0.7)/pi
    const double alpha = -log(0.7) / M_PI;
    const double gam   = alpha / sqrt(alpha * alpha + 1.0);
    const float  eta   = (float)(2.0 * gam * sqrt(500000.0));

    dim3 block(BX, BY, BZ);
    dim3 grid(NG / BX, NG / BY, NG / BZ);
    dem_kernel<<<grid, block>>>(xg, yg, zg, vxg, vyg, vzg, dptr, out, eta);
}